// round 11
// baseline (speedup 1.0000x reference)
#include <cuda_runtime.h>
#include <cuda_fp16.h>
#include <cstdint>

#define B_   128
#define T_   256
#define K_   256
#define NTH  256
#define LOG2E 1.4426950408889634f
#define LN2   0.6931471805599453f

static __device__ __forceinline__ uint32_t packh2(float lo, float hi) {
    __half2 h = __floats2half2_rn(lo, hi);
    return *reinterpret_cast<uint32_t*>(&h);
}
static __device__ __forceinline__ float ex2f(float x) {   // raw MUFU
    float r;
    asm("ex2.approx.f32 %0, %1;" : "=f"(r) : "f"(x));
    return r;
}

__global__ __launch_bounds__(NTH, 1)
void crf_loss_kernel(const float* __restrict__ feats,   // [B,T,K]
                     const float* __restrict__ trans,   // [K,K]
                     const int*   __restrict__ tags,    // [B,T]
                     const int*   __restrict__ lens,    // [B]
                     float*       __restrict__ out)     // [B]
{
    __shared__ __align__(16) __half es[2][K_];   // scaled exp(state), fp16
    __shared__ int   gsh[2];                     // double-buffered log2-normalizer
    __shared__ float red[8];

    const int tid  = threadIdx.x;
    const int lane = tid & 31;
    const int w    = tid >> 5;        // 8 warps
    const int to   = tid;             // one full "to" column per thread
    const int b    = blockIdx.x;

    // ---- ET in registers: ET2[c] = (exp tr[2c][to], exp tr[2c+1][to]) ----
    uint32_t ET2[128];
    {
        const float* tp = trans + to;
        #pragma unroll
        for (int c = 0; c < 128; ++c) {
            float e0 = __expf(__ldg(tp + (size_t)(2 * c)     * K_));
            float e1 = __expf(__ldg(tp + (size_t)(2 * c + 1) * K_));
            ET2[c] = packh2(e0, e1);
        }
    }

    const int len = lens[b];
    const float* fb = feats + (size_t)b * T_ * K_;

    // ---- init: v0 = ex2(f0*log2e - g0), C = g0 ----
    float f0 = fb[to];
    if (tid == 0) gsh[0] = __float2int_rd(f0 * LOG2E) + 14;   // tid0's f0 = f[b,0,0]
    __syncthreads();
    int   g0 = gsh[0];
    int   C  = g0;
    float v  = ex2f(f0 * LOG2E - (float)g0);
    es[0][to] = __float2half_rn(v);

    // distance-2 emission prefetch (values pre-multiplied by log2e)
    const float* fp1 = fb + K_ + to;                   // points at f_{t} for t=1
    float fl2a = (len > 1) ? (fp1[0]  * LOG2E) : 0.f;  // f_1 * log2e
    float fl2b = (len > 2) ? (fp1[K_] * LOG2E) : fl2a; // f_2 * log2e
    __syncthreads();

    // ---- forward recurrence: one barrier per step ----
    for (int t = 1; t < len; ++t) {
        const int p = (t - 1) & 1;
        const int q = t & 1;

        const int gp = gsh[p];
        float efv = ex2f(fl2a - (float)gp);            // MUFU, overlaps matvec
        C += gp;
        // prefetch f_{t+2} (consumed 2 steps from now)
        float fl2n = fl2b;
        if (t + 2 < len)
            fl2n = fp1[2 * K_] * LOG2E;
        fp1 += K_;

        // full matvec for my column: 256 from-values, 4 fp16x2 acc chains
        __half2 zz = __float2half2_rn(0.f);
        __half2 a0 = zz, a1 = zz, a2 = zz, a3 = zz;
        const uint4* ep = reinterpret_cast<const uint4*>(es[p]);
        #pragma unroll
        for (int i = 0; i < 32; ++i) {
            uint4 qv = ep[i];   // warp-uniform broadcast, 1 wavefront
            a0 = __hfma2(*reinterpret_cast<__half2*>(&ET2[4 * i + 0]),
                         *reinterpret_cast<__half2*>(&qv.x), a0);
            a1 = __hfma2(*reinterpret_cast<__half2*>(&ET2[4 * i + 1]),
                         *reinterpret_cast<__half2*>(&qv.y), a1);
            a2 = __hfma2(*reinterpret_cast<__half2*>(&ET2[4 * i + 2]),
                         *reinterpret_cast<__half2*>(&qv.z), a2);
            a3 = __hfma2(*reinterpret_cast<__half2*>(&ET2[4 * i + 3]),
                         *reinterpret_cast<__half2*>(&qv.w), a3);
        }
        a0 = __hadd2(a0, a1);
        a2 = __hadd2(a2, a3);
        a0 = __hadd2(a0, a2);
        float2 fx = __half22float2(a0);
        float s = fx.x + fx.y;

        v = s * efv;                                   // fp32 (subnormal-safe exponent)
        es[q][to] = __float2half_rn(v);
        if (tid == 0)
            gsh[q] = ((__float_as_int(v) >> 23) & 255) - 113;
        fl2a = fl2b;
        fl2b = fl2n;
        __syncthreads();
    }

    // ---- forward_score = logsumexp_{to}(state) ----
    float state = (log2f(v) + (float)C) * LN2;

    float x = state;
    #pragma unroll
    for (int o = 16; o > 0; o >>= 1)
        x = fmaxf(x, __shfl_xor_sync(0xffffffffu, x, o));
    if (lane == 0) red[w] = x;
    __syncthreads();
    float bm = red[0];
    #pragma unroll
    for (int i = 1; i < 8; ++i) bm = fmaxf(bm, red[i]);
    __syncthreads();

    float e = __expf(state - bm);
    #pragma unroll
    for (int o = 16; o > 0; o >>= 1)
        e += __shfl_xor_sync(0xffffffffu, e, o);
    if (lane == 0) red[w] = e;
    __syncthreads();
    float ssum = red[0];
    #pragma unroll
    for (int i = 1; i < 8; ++i) ssum += red[i];
    float forward = bm + __logf(ssum);
    __syncthreads();

    // ---- gold path score: thread tid handles timestep tid (T_ == NTH) ----
    float u = 0.f;
    if (tid < len) {
        int tg = tags[b * T_ + tid];
        u = fb[(size_t)tid * K_ + tg];
        if (tid + 1 < len) {
            int tg2 = tags[b * T_ + tid + 1];
            u += __ldg(trans + (size_t)tg * K_ + tg2);
        }
    }
    #pragma unroll
    for (int o = 16; o > 0; o >>= 1)
        u += __shfl_xor_sync(0xffffffffu, u, o);
    if (lane == 0) red[w] = u;
    __syncthreads();
    if (tid == 0) {
        float us = red[0];
        #pragma unroll
        for (int i = 1; i < 8; ++i) us += red[i];
        out[b] = forward - us;
    }
}

extern "C" void kernel_launch(void* const* d_in, const int* in_sizes, int n_in,
                              void* d_out, int out_size) {
    const float* feats = (const float*)d_in[0];
    const float* trans = (const float*)d_in[1];
    const int*   tags  = (const int*)d_in[2];
    const int*   lens  = (const int*)d_in[3];
    float*       out   = (float*)d_out;

    crf_loss_kernel<<<B_, NTH>>>(feats, trans, tags, lens, out);
}

// round 12
// speedup vs baseline: 1.2028x; 1.2028x over previous
#include <cuda_runtime.h>
#include <cuda_fp16.h>
#include <cstdint>

#define B_   128
#define T_   256
#define K_   256
#define NTH  256
#define LOG2E 1.4426950408889634f
#define LN2   0.6931471805599453f

static __device__ __forceinline__ uint32_t packh2(float lo, float hi) {
    __half2 h = __floats2half2_rn(lo, hi);
    return *reinterpret_cast<uint32_t*>(&h);
}
static __device__ __forceinline__ float ex2f(float x) {   // raw MUFU ex2
    float r;
    asm("ex2.approx.f32 %0, %1;" : "=f"(r) : "f"(x));
    return r;
}

__global__ __launch_bounds__(NTH, 1)
void crf_loss_kernel(const float* __restrict__ feats,   // [B,T,K]
                     const float* __restrict__ trans,   // [K,K]
                     const int*   __restrict__ tags,    // [B,T]
                     const int*   __restrict__ lens,    // [B]
                     float*       __restrict__ out)     // [B]
{
    __shared__ __align__(16) __half es[2][K_];   // scaled exp(state), fp16
    __shared__ int   gsh[2];                     // double-buffered log2-normalizer
    __shared__ float red[8];

    const int tid  = threadIdx.x;
    const int lane = tid & 31;
    const int w    = tid >> 5;        // 8 warps
    const int to   = tid;             // one full "to" column per thread
    const int b    = blockIdx.x;

    // ---- ET in registers: ET2[c] = (exp tr[2c][to], exp tr[2c+1][to]) ----
    // 128 fp16x2 regs per thread; global reads coalesced over `to`.
    uint32_t ET2[128];
    {
        const float* tp = trans + to;
        #pragma unroll
        for (int c = 0; c < 128; ++c) {
            float e0 = __expf(__ldg(tp + (size_t)(2 * c)     * K_));
            float e1 = __expf(__ldg(tp + (size_t)(2 * c + 1) * K_));
            ET2[c] = packh2(e0, e1);
        }
    }

    const int len = lens[b];
    const float* fb = feats + (size_t)b * T_ * K_;

    // ---- init: v0 = ex2(f0*log2e - g0), C = g0 ----
    float f0 = fb[to];
    if (tid == 0) gsh[0] = __float2int_rd(f0 * LOG2E) + 14;   // tid0's f0 = f[b,0,0]
    __syncthreads();
    int   g0 = gsh[0];
    int   C  = g0;
    float v  = ex2f(f0 * LOG2E - (float)g0);
    es[0][to] = __float2half_rn(v);
    float fcur = (len > 1) ? fb[K_ + to] : 0.f;   // prefetch f_1 (coalesced)
    __syncthreads();

    // ---- forward recurrence: one barrier per step ----
    for (int t = 1; t < len; ++t) {
        const int p = (t - 1) & 1;
        const int q = t & 1;

        const int gp = gsh[p];
        float efv = ex2f(fcur * LOG2E - (float)gp);   // MUFU, overlaps matvec
        C += gp;
        const int tn = (t + 1 < len) ? (t + 1) : t;
        float fnext = fb[(size_t)tn * K_ + to];        // prefetch f_{t+1}

        // full matvec for my column: 256 from-values, 4 fp16x2 acc chains
        __half2 zz = __float2half2_rn(0.f);
        __half2 a0 = zz, a1 = zz, a2 = zz, a3 = zz;
        const uint4* ep = reinterpret_cast<const uint4*>(es[p]);
        #pragma unroll
        for (int i = 0; i < 32; ++i) {
            uint4 qv = ep[i];   // warp-uniform broadcast, 1 wavefront
            a0 = __hfma2(*reinterpret_cast<__half2*>(&ET2[4 * i + 0]),
                         *reinterpret_cast<__half2*>(&qv.x), a0);
            a1 = __hfma2(*reinterpret_cast<__half2*>(&ET2[4 * i + 1]),
                         *reinterpret_cast<__half2*>(&qv.y), a1);
            a2 = __hfma2(*reinterpret_cast<__half2*>(&ET2[4 * i + 2]),
                         *reinterpret_cast<__half2*>(&qv.z), a2);
            a3 = __hfma2(*reinterpret_cast<__half2*>(&ET2[4 * i + 3]),
                         *reinterpret_cast<__half2*>(&qv.w), a3);
        }
        a0 = __hadd2(a0, a1);
        a2 = __hadd2(a2, a3);
        a0 = __hadd2(a0, a2);
        float2 fx = __half22float2(a0);
        float s = fx.x + fx.y;

        v = s * efv;
        es[q][to] = __float2half_rn(v);
        if (tid == 0)
            gsh[q] = ((__float_as_int(v) >> 23) & 255) - 113;
        fcur = fnext;
        __syncthreads();
    }

    // ---- forward_score = logsumexp_{to}(state), state = (log2 v + C) ln2 ----
    float state = (log2f(v) + (float)C) * LN2;

    float x = state;
    #pragma unroll
    for (int o = 16; o > 0; o >>= 1)
        x = fmaxf(x, __shfl_xor_sync(0xffffffffu, x, o));
    if (lane == 0) red[w] = x;
    __syncthreads();
    float bm = red[0];
    #pragma unroll
    for (int i = 1; i < 8; ++i) bm = fmaxf(bm, red[i]);
    __syncthreads();

    float e = __expf(state - bm);
    #pragma unroll
    for (int o = 16; o > 0; o >>= 1)
        e += __shfl_xor_sync(0xffffffffu, e, o);
    if (lane == 0) red[w] = e;
    __syncthreads();
    float ssum = red[0];
    #pragma unroll
    for (int i = 1; i < 8; ++i) ssum += red[i];
    float forward = bm + __logf(ssum);
    __syncthreads();

    // ---- gold path score: thread tid handles timestep tid (T_ == NTH) ----
    float u = 0.f;
    if (tid < len) {
        int tg = tags[b * T_ + tid];
        u = fb[(size_t)tid * K_ + tg];
        if (tid + 1 < len) {
            int tg2 = tags[b * T_ + tid + 1];
            u += __ldg(trans + (size_t)tg * K_ + tg2);
        }
    }
    #pragma unroll
    for (int o = 16; o > 0; o >>= 1)
        u += __shfl_xor_sync(0xffffffffu, u, o);
    if (lane == 0) red[w] = u;
    __syncthreads();
    if (tid == 0) {
        float us = red[0];
        #pragma unroll
        for (int i = 1; i < 8; ++i) us += red[i];
        out[b] = forward - us;
    }
}

extern "C" void kernel_launch(void* const* d_in, const int* in_sizes, int n_in,
                              void* d_out, int out_size) {
    const float* feats = (const float*)d_in[0];
    const float* trans = (const float*)d_in[1];
    const int*   tags  = (const int*)d_in[2];
    const int*   lens  = (const int*)d_in[3];
    float*       out   = (float*)d_out;

    crf_loss_kernel<<<B_, NTH>>>(feats, trans, tags, lens, out);
}